// round 7
// baseline (speedup 1.0000x reference)
#include <cuda_runtime.h>
#include <cstdint>

// ---------------------------------------------------------------------------
// TT embedding lookup, persistent-CTA version.
// Work item = (chunk of <=8 samples sharing a core1 row, quarter of the 256KB
// slab). 592 persistent CTAs x 256 threads; each CTA streams its items'
// 64KB quarters through a 3-stage x 16KB smem ring that is refilled
// continuously ACROSS item boundaries (pipeline never drains). Next item's
// metadata and A-pack are prefetched (double buffered) during current item.
// f32x2 FFMA, sample-pair packed accumulators.
// ---------------------------------------------------------------------------

#define NTAB 2
#define BATCH 1024
#define NSAMP (NTAB * BATCH)
#define P12 46656LL
#define NBUCKET (NTAB * 216)
#define CORE1_ROW 65536
#define CHUNK 8
#define MAXCHUNKS 688
#define STAGE_BYTES 16384
#define GRID_W 592

// dynamic smem layout (bytes)
#define SM_BUF    0          // 3 x 16384 = 49152
#define SM_APK    49152      // 2 buffers x 2048 (32 rows x 2 q0 x 4 u64)
#define SM_RED    53248      // 8 warps x 8 samples x 4 floats = 1024
#define SM_META   54272      // 2 x 128
#define SM_FULL   54528      // 3 mbarriers
#define SM_TOTAL  54656

struct Meta { int k; int tbl; int sid[8]; int i0[8]; int i2[8]; int pad[6]; };

__device__ int g_offsets[NBUCKET + 1];
__device__ int g_order[NSAMP];
__device__ int g_i0[NSAMP];
__device__ int g_i2[NSAMP];
__device__ int g_chunk_bucket[MAXCHUNKS];
__device__ int g_chunk_start[MAXCHUNKS];
__device__ int g_nchunks;

// ---------------------------------------------------------------------------
// helpers
// ---------------------------------------------------------------------------
__device__ __forceinline__ unsigned long long pack2(float x, float y) {
    unsigned long long r;
    asm("mov.b64 %0, {%1, %2};" : "=l"(r) : "f"(x), "f"(y));
    return r;
}
__device__ __forceinline__ void unpack2(unsigned long long v, float& x, float& y) {
    asm("mov.b64 {%0, %1}, %2;" : "=f"(x), "=f"(y) : "l"(v));
}
__device__ __forceinline__ void ffma2(unsigned long long& d,
                                      unsigned long long a,
                                      unsigned long long b) {
    asm("fma.rn.f32x2 %0, %1, %2, %0;" : "+l"(d) : "l"(a), "l"(b));
}
__device__ __forceinline__ void mbar_init(uint32_t a, uint32_t cnt) {
    asm volatile("mbarrier.init.shared.b64 [%0], %1;" :: "r"(a), "r"(cnt) : "memory");
}
__device__ __forceinline__ void mbar_expect(uint32_t a, uint32_t bytes) {
    asm volatile("mbarrier.arrive.expect_tx.shared.b64 _, [%0], %1;"
                 :: "r"(a), "r"(bytes) : "memory");
}
__device__ __forceinline__ void mbar_wait(uint32_t a, uint32_t ph) {
    uint32_t done;
    asm volatile(
        "{\n\t.reg .pred p;\n\t"
        "mbarrier.try_wait.parity.acquire.cta.shared::cta.b64 p, [%1], %2;\n\t"
        "selp.b32 %0, 1, 0, p;\n\t}"
        : "=r"(done) : "r"(a), "r"(ph) : "memory");
    if (!done) {
        asm volatile(
            "{\n\t.reg .pred P1;\n"
            "W%=:\n\t"
            "mbarrier.try_wait.parity.acquire.cta.shared::cta.b64 P1, [%0], %1, 0x989680;\n\t"
            "@P1 bra.uni D%=;\n\t"
            "bra.uni W%=;\n"
            "D%=:\n\t}"
            :: "r"(a), "r"(ph) : "memory");
    }
}
__device__ __forceinline__ void bulk_copy(uint32_t dst, const void* src,
                                          uint32_t bytes, uint32_t mbar) {
    asm volatile(
        "cp.async.bulk.shared::cta.global.mbarrier::complete_tx::bytes [%0], [%1], %2, [%3];"
        :: "r"(dst), "l"(src), "r"(bytes), "r"(mbar) : "memory");
}

// ---------------------------------------------------------------------------
// Phase A: decode, bucket-sort (smem atomics), build chunk list, zero output.
// (unchanged from R5 — proven correct)
// ---------------------------------------------------------------------------
__global__ void build_buckets(const void* __restrict__ idx_raw,
                              float* __restrict__ out) {
    const int tid = threadIdx.x;  // 1024
    __shared__ int   scnt[512];
    __shared__ int   schk[512];
    __shared__ int   scur[NBUCKET];
    __shared__ short sbk[NSAMP];

    float4* o4 = (float4*)out;
    #pragma unroll
    for (int i = tid; i < NSAMP * 4; i += 1024)
        o4[i] = make_float4(0.f, 0.f, 0.f, 0.f);

    if (tid < 512) scnt[tid] = 0;
    __syncthreads();

    const long long* p64 = (const long long*)idx_raw;
    const int*       p32 = (const int*)idx_raw;
    bool is64 = true;
    #pragma unroll
    for (int j = 0; j < 4; j++) {
        long long v = p64[j];
        if (v < 0 || v >= 10000000LL) is64 = false;
    }

    for (int s = tid; s < NSAMP; s += 1024) {
        long long idx = is64 ? p64[s] : (long long)p32[s];
        int i0 = (int)(idx / P12);
        int i1 = (int)((idx / 216) % 216);
        int i2 = (int)(idx % 216);
        int b = (s >> 10) * 216 + i1;
        g_i0[s] = i0;
        g_i2[s] = i2;
        sbk[s] = (short)b;
        atomicAdd(&scnt[b], 1);
    }
    __syncthreads();

    int mycnt = 0;
    if (tid < 512) {
        mycnt = scnt[tid];
        schk[tid] = (mycnt + CHUNK - 1) / CHUNK;
    }
    __syncthreads();
    for (int d = 1; d < 512; d <<= 1) {
        int a = 0, b = 0;
        if (tid < 512 && tid >= d) { a = scnt[tid - d]; b = schk[tid - d]; }
        __syncthreads();
        if (tid < 512 && tid >= d) { scnt[tid] += a; schk[tid] += b; }
        __syncthreads();
    }

    if (tid < NBUCKET) {
        int off = scnt[tid] - mycnt;
        g_offsets[tid] = off;
        scur[tid] = off;
        int nch = (mycnt + CHUNK - 1) / CHUNK;
        int chkoff = schk[tid] - nch;
        for (int j = 0; j < nch; j++) {
            g_chunk_bucket[chkoff + j] = tid;
            g_chunk_start[chkoff + j]  = off + j * CHUNK;
        }
    }
    if (tid == 0) g_offsets[NBUCKET] = NSAMP;
    __syncthreads();
    if (tid == 0) g_nchunks = schk[511];
    __syncthreads();

    for (int s = tid; s < NSAMP; s += 1024) {
        int pos = atomicAdd(&scur[(int)sbk[s]], 1);
        g_order[pos] = s;
    }
}

// ---------------------------------------------------------------------------
// meta load for item m into buffer pb (threads t<8)
// ---------------------------------------------------------------------------
__device__ __forceinline__ void load_meta(char* smem, int pb, int m, int t) {
    if (t >= 8) return;
    Meta* M = (Meta*)(smem + SM_META) + pb;
    int c = m >> 2;
    int bucket = g_chunk_bucket[c];
    int cs = g_chunk_start[c];
    int end = g_offsets[bucket + 1];
    int k = min(CHUNK, end - cs);
    if (t < k) {
        int sid = g_order[cs + t];
        M->sid[t] = sid;
        M->i0[t]  = g_i0[sid];
        M->i2[t]  = g_i2[sid];
    } else {
        M->sid[t] = 0; M->i0[t] = 0; M->i2[t] = 0;
    }
    if (t == 0) { M->k = k; M->tbl = (bucket >= 216) ? 216 * 256 : 0; }
}

// A-pack float slot decode: f -> value. apk float layout:
// f = ((Lr*2+q0)*4 + s/2)*2 + (s&1), Lr in [0,32), q0 in [0,2), s in [0,8)
__device__ __forceinline__ float fetch_A(const float* __restrict__ core0,
                                         const Meta* M, int qq, int f) {
    int l  = f & 1;
    int e  = f >> 1;
    int sp = e & 3;
    int q0 = (e >> 2) & 1;
    int Lr = e >> 3;
    int s  = sp * 2 + l;
    if (s >= M->k) return 0.0f;
    return __ldg(core0 + M->tbl + (size_t)M->i0[s] * 256 + q0 * 128 + qq * 32 + Lr);
}

// ---------------------------------------------------------------------------
// item body: 4 stages of 8 rows + epilogue. K2U in {2,4} (sample pairs).
// Overlap tasks per stage region (after that stage's __syncthreads):
//   ss0: refill x+3, load meta(next item)
//   ss1: refill x+3, LDG A(next item) into regs
//   ss2: refill x+3, STS A regs -> apk[pb^1]
//   ss3: refill x+3, then epilogue
// ---------------------------------------------------------------------------
template <int K2U>
__device__ __forceinline__ void item_body(
    char* smem, uint32_t smem_u32, int i, int pb, int m, int nitems,
    const float* __restrict__ core0,
    const float* __restrict__ core1,
    const float* __restrict__ core2,
    float* __restrict__ out) {

    const int t    = threadIdx.x;
    const int bx   = blockIdx.x;
    const int lane = t & 31;
    const int warp = t >> 5;
    const uint32_t mb_full = smem_u32 + SM_FULL;
    const Meta* M = (const Meta*)(smem + SM_META) + pb;
    const int mn = m + GRID_W;            // next item id
    const bool has_next = (mn < nitems);

    unsigned long long acc[K2U][2][2];
    #pragma unroll
    for (int sp = 0; sp < K2U; sp++)
        #pragma unroll
        for (int q0 = 0; q0 < 2; q0++) { acc[sp][q0][0] = 0ULL; acc[sp][q0][1] = 0ULL; }

    float apre0 = 0.f, apre1 = 0.f;

    #pragma unroll 1
    for (int ss = 0; ss < 4; ss++) {
        const int x = 4 * i + ss;
        const int xd3 = x / 3;
        const int buf = x - xd3 * 3;
        mbar_wait(mb_full + buf * 8, xd3 & 1);

        #pragma unroll
        for (int rr = 0; rr < 8; rr++) {
            float2 b = *(const float2*)(smem + SM_BUF + buf * STAGE_BYTES
                                        + rr * 2048 + t * 8);
            unsigned long long b0 = pack2(b.x, b.x);
            unsigned long long b1 = pack2(b.y, b.y);
            const ulonglong2* ar = (const ulonglong2*)(smem + SM_APK + pb * 2048
                                                       + (ss * 8 + rr) * 64);
            #pragma unroll
            for (int q0 = 0; q0 < 2; q0++) {
                ulonglong2 aa = ar[q0 * 2];
                ffma2(acc[0][q0][0], b0, aa.x);
                ffma2(acc[0][q0][1], b1, aa.x);
                ffma2(acc[1][q0][0], b0, aa.y);
                ffma2(acc[1][q0][1], b1, aa.y);
                if (K2U > 2) {
                    ulonglong2 ab = ar[q0 * 2 + 1];
                    ffma2(acc[2][q0][0], b0, ab.x);
                    ffma2(acc[2][q0][1], b1, ab.x);
                    ffma2(acc[3][q0][0], b0, ab.y);
                    ffma2(acc[3][q0][1], b1, ab.y);
                }
            }
        }
        __syncthreads();

        // continuous refill: stage x+3 (may belong to the next item)
        if (t == 0) {
            int xn = x + 3;
            int inn = xn >> 2;
            int m2 = bx + inn * GRID_W;
            if (m2 < nitems) {
                int c2 = m2 >> 2, q2v = m2 & 3;
                int bkt = g_chunk_bucket[c2];
                const float* src = core1 + (size_t)bkt * CORE1_ROW
                                 + (size_t)q2v * 16384 + (size_t)(xn & 3) * 4096;
                uint32_t mb = mb_full + buf * 8;   // (x+3)%3 == x%3
                mbar_expect(mb, STAGE_BYTES);
                bulk_copy(smem_u32 + SM_BUF + buf * STAGE_BYTES, src,
                          STAGE_BYTES, mb);
            }
        }
        if (ss == 0 && has_next) load_meta(smem, pb ^ 1, mn, t);
        if (ss == 1 && has_next) {
            const Meta* Mn = (const Meta*)(smem + SM_META) + (pb ^ 1);
            int qq = mn & 3;
            apre0 = fetch_A(core0, Mn, qq, t);
            apre1 = fetch_A(core0, Mn, qq, t + 256);
        }
        if (ss == 2 && has_next) {
            float* ap = (float*)(smem + SM_APK + (pb ^ 1) * 2048);
            ap[t] = apre0;
            ap[t + 256] = apre1;
        }
    }

    // ---- epilogue ----
    float* s_red = (float*)(smem + SM_RED);
    const int r1p = t & 63;
    const int k = M->k;

    #pragma unroll
    for (int sp = 0; sp < K2U; sp++) {
        float x00, x01, x10, x11, y00, y01, y10, y11;
        unpack2(acc[sp][0][0], x00, y00);
        unpack2(acc[sp][0][1], x01, y01);
        unpack2(acc[sp][1][0], x10, y10);
        unpack2(acc[sp][1][1], x11, y11);
        #pragma unroll
        for (int h2 = 0; h2 < 2; h2++) {
            int s = 2 * sp + h2;
            const float* c2row = core2 + M->tbl + (size_t)M->i2[s] * 256;
            float4 cv = __ldg((const float4*)(c2row + r1p * 4));
            float A0 = h2 ? y00 : x00, A1 = h2 ? y01 : x01;
            float B0 = h2 ? y10 : x10, B1 = h2 ? y11 : x11;
            float p00 = fmaf(A0, cv.x, A1 * cv.z);
            float p01 = fmaf(A0, cv.y, A1 * cv.w);
            float p10 = fmaf(B0, cv.x, B1 * cv.z);
            float p11 = fmaf(B0, cv.y, B1 * cv.w);
            #pragma unroll
            for (int off = 16; off > 0; off >>= 1) {
                p00 += __shfl_xor_sync(0xFFFFFFFFu, p00, off);
                p01 += __shfl_xor_sync(0xFFFFFFFFu, p01, off);
                p10 += __shfl_xor_sync(0xFFFFFFFFu, p10, off);
                p11 += __shfl_xor_sync(0xFFFFFFFFu, p11, off);
            }
            if (lane == 0) {
                float* r = s_red + (warp * 8 + s) * 4;
                r[0] = p00; r[1] = p01; r[2] = p10; r[3] = p11;
            }
        }
    }
    __syncthreads();

    if (t < k * 16) {
        int s = t >> 4, j = t & 15;
        int q0 = j >> 3, q1 = (j >> 1) & 3, q2 = j & 1;
        int idx = q0 * 2 + q2;
        int w0 = 2 * q1;
        float v = s_red[((w0)     * 8 + s) * 4 + idx]
                + s_red[((w0 + 1) * 8 + s) * 4 + idx];
        atomicAdd(&out[(size_t)M->sid[s] * 16 + j], v);
    }
    // no trailing sync needed: next item's stage-0 barrier orders reuse.
}

// ---------------------------------------------------------------------------
// Persistent worker
// ---------------------------------------------------------------------------
__global__ __launch_bounds__(256, 4) void tt_persist(
    const float* __restrict__ core0,
    const float* __restrict__ core1,
    const float* __restrict__ core2,
    float* __restrict__ out) {

    extern __shared__ char smem[];
    const int t  = threadIdx.x;
    const int bx = blockIdx.x;
    const int nitems = 4 * g_nchunks;
    if (bx >= nitems) return;

    const uint32_t smem_u32 = (uint32_t)__cvta_generic_to_shared(smem);

    // t0: init mbarriers + issue first 3 stage copies (item 0: stages 0..2)
    if (t == 0) {
        #pragma unroll
        for (int j = 0; j < 3; j++) mbar_init(smem_u32 + SM_FULL + j * 8, 1);
        asm volatile("fence.proxy.async.shared::cta;" ::: "memory");
        int c0i = bx >> 2, q0i = bx & 3;
        int bkt = g_chunk_bucket[c0i];
        const float* base = core1 + (size_t)bkt * CORE1_ROW + (size_t)q0i * 16384;
        #pragma unroll
        for (int j = 0; j < 3; j++) {
            uint32_t mb = smem_u32 + SM_FULL + j * 8;
            mbar_expect(mb, STAGE_BYTES);
            bulk_copy(smem_u32 + SM_BUF + j * STAGE_BYTES,
                      base + (size_t)j * 4096, STAGE_BYTES, mb);
        }
    }
    load_meta(smem, 0, bx, t);
    __syncthreads();

    // A-pack for item 0
    {
        const Meta* M0 = (const Meta*)(smem + SM_META);
        int qq = bx & 3;
        float v0 = fetch_A(core0, M0, qq, t);
        float v1 = fetch_A(core0, M0, qq, t + 256);
        float* ap = (float*)(smem + SM_APK);
        ap[t] = v0;
        ap[t + 256] = v1;
    }
    __syncthreads();

    int i = 0;
    for (int m = bx; m < nitems; m += GRID_W, i++) {
        const int pb = i & 1;
        const Meta* M = (const Meta*)(smem + SM_META) + pb;
        if (M->k <= 4)
            item_body<2>(smem, smem_u32, i, pb, m, nitems,
                         core0, core1, core2, out);
        else
            item_body<4>(smem, smem_u32, i, pb, m, nitems,
                         core0, core1, core2, out);
    }
}

// ---------------------------------------------------------------------------
// Launch
// ---------------------------------------------------------------------------
extern "C" void kernel_launch(void* const* d_in, const int* in_sizes, int n_in,
                              void* d_out, int out_size) {
    (void)in_sizes; (void)n_in; (void)out_size;
    const void*  idx   = d_in[0];                 // lS_i [2,1024] int64 (or int32)
    const float* core0 = (const float*)d_in[1];   // [2,216,256]
    const float* core1 = (const float*)d_in[2];   // [2,216,65536]
    const float* core2 = (const float*)d_in[3];   // [2,216,256]
    float* out = (float*)d_out;                   // [2,1024,16]

    cudaFuncSetAttribute(tt_persist, cudaFuncAttributeMaxDynamicSharedMemorySize,
                         SM_TOTAL);

    build_buckets<<<1, 1024>>>(idx, out);
    tt_persist<<<GRID_W, 256, SM_TOTAL>>>(core0, core1, core2, out);
}